// round 12
// baseline (speedup 1.0000x reference)
#include <cuda_runtime.h>
#include <cuda_bf16.h>
#include <cuda_fp8.h>
#include <cstdint>

// ContrastiveLoss (NT-Xent), fully fused persistent kernel.
// Phase 1: L2-normalize rows -> g_zn (fp32) + g_z8 (e4m3 * 16)
// Phase 2: sim = z z^T upper-triangle 128x128 tiles, FP8 mma, fused
//          exp + diag-mask + row/col partial sums, cp.async double-buffered
// Phase 3: per-row loss + global mean -> out
// Grid = 296 blocks (2/SM x 148 SMs; <= resident capacity on B300 & GB300),
// software grid barriers (monotonic generation counter, graph-replay safe).

#define NB     4096
#define TN     8192
#define D      128
#define CB     64
#define NT     64
#define NBLK   2080          // NT*(NT+1)/2 triangle tiles
#define NBLKP  296           // persistent blocks
#define LDB    144           // smem tile stride bytes (128+16 pad)
#define TILEB  (128 * LDB)   // 18432 B per tile
#define STAGEB (2 * TILEB)   // A+B per stage
#define SMEMB  (2 * STAGEB + 3072)   // 2 stages + reduction scratch
#define EXS    0.0078125f    // (1/TEMP) / (16*16)
#define INVT   2.0f

__device__ float    g_zn[TN * D];
__device__ uint32_t g_z8[TN * D / 4];
__device__ float    g_part[TN * CB];
__device__ float    g_lpart[NBLKP];
__device__ unsigned g_arrive = 0;
__device__ volatile unsigned g_gen = 0;

__device__ __forceinline__ float wred(float v) {
#pragma unroll
    for (int o = 16; o > 0; o >>= 1) v += __shfl_xor_sync(0xFFFFFFFFu, v, o);
    return v;
}

__device__ __forceinline__ uint32_t pack_e4m3x4(float x, float y, float z, float w) {
    uint16_t lo, hi;
    asm("cvt.rn.satfinite.e4m3x2.f32 %0, %1, %2;" : "=h"(lo) : "f"(y), "f"(x));
    asm("cvt.rn.satfinite.e4m3x2.f32 %0, %1, %2;" : "=h"(hi) : "f"(w), "f"(z));
    return (uint32_t)lo | ((uint32_t)hi << 16);
}

__device__ __forceinline__ void cpasync16(uint32_t smem_dst, const void* gsrc) {
    asm volatile("cp.async.cg.shared.global [%0], [%1], 16;"
                 :: "r"(smem_dst), "l"(gsrc));
}

__device__ __forceinline__ void ldsm4(uint32_t addr, uint32_t& r0, uint32_t& r1,
                                      uint32_t& r2, uint32_t& r3) {
    asm volatile("ldmatrix.sync.aligned.m8n8.x4.shared.b16 {%0,%1,%2,%3}, [%4];"
                 : "=r"(r0), "=r"(r1), "=r"(r2), "=r"(r3) : "r"(addr));
}

__device__ __forceinline__ void gridbar(unsigned target) {
    __syncthreads();
    if (threadIdx.x == 0) {
        __threadfence();
        unsigned old = atomicAdd(&g_arrive, 1u);
        if (old == NBLKP - 1) {
            g_arrive = 0;
            __threadfence();
            g_gen = target;
        } else {
            while (g_gen < target) __nanosleep(64);
        }
        __threadfence();
    }
    __syncthreads();
}

__device__ __forceinline__ void tile_decode(int t, int& br, int& bc) {
    int b = t, r = 0;
    while (b >= NT - r) { b -= NT - r; ++r; }
    br = r; bc = r + b;
}

__global__ void __launch_bounds__(256, 2) kfused(
    const float* __restrict__ p1, const float* __restrict__ p2,
    float* __restrict__ out) {
    extern __shared__ uint8_t sm[];
    const uint32_t smbase = (uint32_t)__cvta_generic_to_shared(sm);
    float* scratch = reinterpret_cast<float*>(sm + 2 * STAGEB);

    const int tid  = threadIdx.x;
    const int wid  = tid >> 5;
    const int lane = tid & 31;
    const int bid  = blockIdx.x;

    __shared__ unsigned s_g0;
    if (tid == 0) s_g0 = g_gen;
    __syncthreads();
    const unsigned g0 = s_g0;

    // ---------------- Phase 1: normalize (warp per row) ----------------
    for (int rb = bid; rb < TN / 8; rb += NBLKP) {
        int r = rb * 8 + wid;
        const float* src = (r < NB) ? (p1 + (size_t)r * D) : (p2 + (size_t)(r - NB) * D);
        float4 v = reinterpret_cast<const float4*>(src)[lane];
        float ss = v.x * v.x + v.y * v.y + v.z * v.z + v.w * v.w;
        ss = wred(ss);
        float inv = 1.0f / fmaxf(sqrtf(ss), 1e-12f);
        v.x *= inv; v.y *= inv; v.z *= inv; v.w *= inv;
        reinterpret_cast<float4*>(g_zn + (size_t)r * D)[lane] = v;
        g_z8[(size_t)r * (D / 4) + lane] =
            pack_e4m3x4(v.x * 16.f, v.y * 16.f, v.z * 16.f, v.w * 16.f);
    }
    gridbar(g0 + 1);

    // ------- Phase 2: triangle tiles, double-buffered cp.async -------
    const int g      = lane >> 2;
    const int tc     = lane & 3;
    const int lrow   = lane & 7;
    const int lt     = lane >> 3;
    const int warp_m = wid & 3;
    const int warp_n = wid >> 2;

    {
        int t = bid, stage = 0;
        if (t < NBLK) {                       // prologue loads
            int br, bc; tile_decode(t, br, bc);
            uint32_t dA = smbase, dB = smbase + TILEB;
#pragma unroll
            for (int i = 0; i < 4; ++i) {
                int idx = tid + i * 256;
                int row = idx >> 3, u4 = idx & 7;
                cpasync16(dA + row * LDB + u4 * 16,
                          reinterpret_cast<const uint4*>(&g_z8[(size_t)((br << 7) + row) * (D / 4)]) + u4);
                cpasync16(dB + row * LDB + u4 * 16,
                          reinterpret_cast<const uint4*>(&g_z8[(size_t)((bc << 7) + row) * (D / 4)]) + u4);
            }
            asm volatile("cp.async.commit_group;");
        }
        for (; t < NBLK; t += NBLKP) {
            int br, bc; tile_decode(t, br, bc);
            const int r0 = br << 7, c0 = bc << 7;
            int t2 = t + NBLKP;
            if (t2 < NBLK) {                  // prefetch next tile
                int nr, nc; tile_decode(t2, nr, nc);
                uint32_t dA = smbase + (stage ^ 1) * STAGEB, dB = dA + TILEB;
#pragma unroll
                for (int i = 0; i < 4; ++i) {
                    int idx = tid + i * 256;
                    int row = idx >> 3, u4 = idx & 7;
                    cpasync16(dA + row * LDB + u4 * 16,
                              reinterpret_cast<const uint4*>(&g_z8[(size_t)((nr << 7) + row) * (D / 4)]) + u4);
                    cpasync16(dB + row * LDB + u4 * 16,
                              reinterpret_cast<const uint4*>(&g_z8[(size_t)((nc << 7) + row) * (D / 4)]) + u4);
                }
                asm volatile("cp.async.commit_group;");
                asm volatile("cp.async.wait_group 1;");
            } else {
                asm volatile("cp.async.wait_group 0;");
            }
            __syncthreads();

            const uint32_t smA = smbase + stage * STAGEB;
            const uint32_t smB = smA + TILEB;
            uint32_t aBase[2];
#pragma unroll
            for (int tm = 0; tm < 2; ++tm)
                aBase[tm] = smA + (warp_m * 32 + tm * 16 + lrow + (lt & 1) * 8) * LDB
                                + (lt >> 1) * 16;
            uint32_t bBase[4];
#pragma unroll
            for (int tp = 0; tp < 4; ++tp)
                bBase[tp] = smB + (warp_n * 64 + tp * 16 + lrow + (lt >> 1) * 8) * LDB
                                + (lt & 1) * 16;

            float c[2][8][4];
#pragma unroll
            for (int i = 0; i < 2; ++i)
#pragma unroll
                for (int j = 0; j < 8; ++j)
#pragma unroll
                    for (int q = 0; q < 4; ++q) c[i][j][q] = 0.f;

#pragma unroll
            for (int ks = 0; ks < 4; ++ks) {
                const uint32_t kOff = ks * 32;
                uint32_t b0[8], b1[8];
#pragma unroll
                for (int tp = 0; tp < 4; ++tp)
                    ldsm4(bBase[tp] + kOff, b0[tp * 2], b1[tp * 2],
                          b0[tp * 2 + 1], b1[tp * 2 + 1]);
#pragma unroll
                for (int tm = 0; tm < 2; ++tm) {
                    uint32_t a0, a1, a2, a3;
                    ldsm4(aBase[tm] + kOff, a0, a1, a2, a3);
#pragma unroll
                    for (int tn = 0; tn < 8; ++tn) {
                        asm volatile(
                            "mma.sync.aligned.m16n8k32.row.col.f32.e4m3.e4m3.f32 "
                            "{%0,%1,%2,%3}, {%4,%5,%6,%7}, {%8,%9}, {%0,%1,%2,%3};\n"
                            : "+f"(c[tm][tn][0]), "+f"(c[tm][tn][1]),
                              "+f"(c[tm][tn][2]), "+f"(c[tm][tn][3])
                            : "r"(a0), "r"(a1), "r"(a2), "r"(a3),
                              "r"(b0[tn]), "r"(b1[tn]));
                    }
                }
            }

            // epilogue: exp + mask + row/col partials
            float rs[2][2] = {{0.f, 0.f}, {0.f, 0.f}};
            float cs[16];
#pragma unroll
            for (int i = 0; i < 16; ++i) cs[i] = 0.f;
#pragma unroll
            for (int tm = 0; tm < 2; ++tm) {
#pragma unroll
                for (int tn = 0; tn < 8; ++tn) {
                    int gcb = c0 + warp_n * 64 + tn * 8 + tc * 2;
                    int gr0 = r0 + warp_m * 32 + tm * 16 + g;
                    float e00 = __expf(EXS * c[tm][tn][0]);
                    float e01 = __expf(EXS * c[tm][tn][1]);
                    float e10 = __expf(EXS * c[tm][tn][2]);
                    float e11 = __expf(EXS * c[tm][tn][3]);
                    rs[tm][0] += (gr0     != gcb    ) ? e00 : 0.f;
                    rs[tm][0] += (gr0     != gcb + 1) ? e01 : 0.f;
                    rs[tm][1] += (gr0 + 8 != gcb    ) ? e10 : 0.f;
                    rs[tm][1] += (gr0 + 8 != gcb + 1) ? e11 : 0.f;
                    cs[tn * 2 + 0] += e00 + e10;
                    cs[tn * 2 + 1] += e01 + e11;
                }
            }
#pragma unroll
            for (int tm = 0; tm < 2; ++tm)
#pragma unroll
                for (int rh = 0; rh < 2; ++rh) {
                    float v = rs[tm][rh];
                    v += __shfl_xor_sync(0xFFFFFFFFu, v, 1);
                    v += __shfl_xor_sync(0xFFFFFFFFu, v, 2);
                    rs[tm][rh] = v;
                }
#pragma unroll
            for (int i = 0; i < 16; ++i) {
                float v = cs[i];
                v += __shfl_xor_sync(0xFFFFFFFFu, v, 4);
                v += __shfl_xor_sync(0xFFFFFFFFu, v, 8);
                v += __shfl_xor_sync(0xFFFFFFFFu, v, 16);
                cs[i] = v;
            }

            float* rowred = scratch;          // [2][128]
            float* colred = scratch + 256;    // [8][64]
            if (tc == 0) {
#pragma unroll
                for (int tm = 0; tm < 2; ++tm)
#pragma unroll
                    for (int rh = 0; rh < 2; ++rh) {
                        int rb2 = warp_m * 32 + tm * 16 + rh * 8 + g;
                        rowred[warp_n * 128 + rb2] = rs[tm][rh];
                    }
            }
            if (g == 0) {
#pragma unroll
                for (int tn = 0; tn < 8; ++tn)
#pragma unroll
                    for (int j = 0; j < 2; ++j)
                        colred[wid * 64 + tn * 8 + tc * 2 + j] = cs[tn * 2 + j];
            }
            __syncthreads();
            if (tid < 128) {
                float rv = rowred[tid] + rowred[128 + tid];
                g_part[(size_t)(r0 + tid) * CB + bc] = rv;
                if (br != bc) {
                    int strip = tid >> 6, ci = tid & 63;
                    float cv = colred[(strip * 4 + 0) * 64 + ci]
                             + colred[(strip * 4 + 1) * 64 + ci]
                             + colred[(strip * 4 + 2) * 64 + ci]
                             + colred[(strip * 4 + 3) * 64 + ci];
                    g_part[(size_t)(c0 + tid) * CB + br] = cv;
                }
            }
            stage ^= 1;
        }
    }
    gridbar(g0 + 2);

    // ---------------- Phase 3: per-row loss + mean ----------------
    float lsum = 0.f;
    for (int rb = bid; rb < TN / 8; rb += NBLKP) {
        int r = rb * 8 + wid;
        float d = g_part[(size_t)r * CB + lane] + g_part[(size_t)r * CB + lane + 32];
        d = wred(d);
        int p = (r < NB) ? (r + NB) : (r - NB);
        float4 a = reinterpret_cast<const float4*>(g_zn + (size_t)r * D)[lane];
        float4 b = reinterpret_cast<const float4*>(g_zn + (size_t)p * D)[lane];
        float pos = a.x * b.x + a.y * b.y + a.z * b.z + a.w * b.w;
        pos = wred(pos);
        if (lane == 0) lsum += -INVT * pos + logf(d);
    }
    if (lane == 0) scratch[wid] = lsum;
    __syncthreads();
    if (tid == 0) {
        float tsum = 0.f;
#pragma unroll
        for (int i = 0; i < 8; ++i) tsum += scratch[i];
        g_lpart[bid] = tsum;
    }
    gridbar(g0 + 3);

    if (bid == 0) {
        float v = (tid < NBLKP) ? g_lpart[tid] : 0.f;
        if (tid + 256 < NBLKP) v += g_lpart[tid + 256];
        v = wred(v);
        if ((tid & 31) == 0) scratch[tid >> 5] = v;
        __syncthreads();
        if (tid == 0) {
            float x = 0.f;
#pragma unroll
            for (int i = 0; i < 8; ++i) x += scratch[i];
            out[0] = x / (float)TN;
        }
    }
}

extern "C" void kernel_launch(void* const* d_in, const int* in_sizes, int n_in,
                              void* d_out, int out_size) {
    const float* p1 = (const float*)d_in[0];
    const float* p2 = (const float*)d_in[1];
    float* out = (float*)d_out;

    static bool attr_set = false;
    if (!attr_set) {
        cudaFuncSetAttribute(kfused, cudaFuncAttributeMaxDynamicSharedMemorySize, SMEMB);
        attr_set = true;
    }
    kfused<<<NBLKP, 256, SMEMB>>>(p1, p2, out);
}